// round 17
// baseline (speedup 1.0000x reference)
#include <cuda_runtime.h>
#include <cuda_bf16.h>
#include <cstdint>
#include <cstddef>

#define BS   256
#define HID  1024
#define NT   100
#define ACT  32
#define KIN  8000
#define G3   3072
#define OUTD 64

// ---------------- device scratch (allocation-free rule) ----------------
__device__ float g_h0[BS * HID];
__device__ float g_h0p[2 * BS * HID];
__device__ unsigned g_bars[4 * 32];

__device__ __align__(16) unsigned short g_obf_hi[(size_t)NT * BS * HID];
__device__ __align__(16) unsigned short g_obf_lo[(size_t)NT * BS * HID];
__device__ __align__(16) unsigned short g_h0b_hi[BS * HID];
__device__ __align__(16) unsigned short g_h0b_lo[BS * HID];
__device__ __align__(16) unsigned short g_wBp_hi[32 * HID * 96];
__device__ __align__(16) unsigned short g_wBp_lo[32 * HID * 96];
__device__ __align__(16) unsigned short g_wo_hi[HID * OUTD];
__device__ __align__(16) unsigned short g_wo_lo[HID * OUTD];
__device__ __align__(16) unsigned short g_win_hi[(size_t)KIN * HID];
__device__ __align__(16) unsigned short g_win_lo[(size_t)KIN * HID];
__device__ __align__(16) unsigned short g_x_hi[BS * KIN];
__device__ __align__(16) unsigned short g_x_lo[BS * KIN];

// ---------------- helpers ----------------
__device__ __forceinline__ float fast_sigmoid(float x) {
    return __fdividef(1.0f, 1.0f + __expf(-x));
}
__device__ __forceinline__ float fast_tanh(float x) {
    float e = __expf(2.0f * x);
    return 1.0f - __fdividef(2.0f, e + 1.0f);
}
__device__ __forceinline__ void split2(float x, unsigned short& h, unsigned short& l) {
    __nv_bfloat16 hb = __float2bfloat16(x);
    float hf = __bfloat162float(hb);
    __nv_bfloat16 lb = __float2bfloat16(x - hf);
    h = *reinterpret_cast<unsigned short*>(&hb);
    l = *reinterpret_cast<unsigned short*>(&lb);
}
__device__ __forceinline__ void split8(const float* src, uint4& H, uint4& L) {
    unsigned short* ph = (unsigned short*)&H;
    unsigned short* pl = (unsigned short*)&L;
    float4 v0 = *reinterpret_cast<const float4*>(src);
    float4 v1 = *reinterpret_cast<const float4*>(src + 4);
    split2(v0.x, ph[0], pl[0]); split2(v0.y, ph[1], pl[1]);
    split2(v0.z, ph[2], pl[2]); split2(v0.w, ph[3], pl[3]);
    split2(v1.x, ph[4], pl[4]); split2(v1.y, ph[5], pl[5]);
    split2(v1.z, ph[6], pl[6]); split2(v1.w, ph[7], pl[7]);
}

#define CP16(dst, src) asm volatile("cp.async.cg.shared.global [%0], [%1], 16;\n" :: "r"(dst), "l"(src))
#define CP_COMMIT()    asm volatile("cp.async.commit_group;\n")
#define CP_WAIT(n)     asm volatile("cp.async.wait_group %0;\n" :: "n"(n))

__device__ __forceinline__ uint32_t smem_u32(const void* p) {
    uint32_t a;
    asm("{ .reg .u64 t; cvta.to.shared.u64 t, %1; cvt.u32.u64 %0, t; }" : "=r"(a) : "l"(p));
    return a;
}
__device__ __forceinline__ void mma16816(float* c, const uint32_t* a, const uint32_t* b) {
    asm volatile("mma.sync.aligned.m16n8k16.row.col.f32.bf16.bf16.f32 "
        "{%0,%1,%2,%3}, {%4,%5,%6,%7}, {%8,%9}, {%0,%1,%2,%3};"
        : "+f"(c[0]), "+f"(c[1]), "+f"(c[2]), "+f"(c[3])
        : "r"(a[0]), "r"(a[1]), "r"(a[2]), "r"(a[3]), "r"(b[0]), "r"(b[1]));
}
#define LDSM4(r, addr)                                                          \
    asm volatile("ldmatrix.sync.aligned.m8n8.x4.shared.b16 {%0,%1,%2,%3}, [%4];"\
        : "=r"((r)[0]), "=r"((r)[1]), "=r"((r)[2]), "=r"((r)[3]) : "r"(addr))
#define LDSM4T(r, addr)                                                         \
    asm volatile("ldmatrix.sync.aligned.m8n8.x4.trans.shared.b16 {%0,%1,%2,%3}, [%4];" \
        : "=r"((r)[0]), "=r"((r)[1]), "=r"((r)[2]), "=r"((r)[3]) : "r"(addr))

// ===========================================================================
// k_prep: merged elementwise prep — barrier zero + cvtX + packWin + packWo
// + packW (Wh gather). 8 elems/thread.
// ===========================================================================
#define NXV  ((size_t)BS * KIN / 8)              // 256000
#define NWV  ((size_t)KIN * HID / 8)             // 1024000
#define NOV  ((size_t)HID * OUTD / 8)            // 8192
#define NPW  ((size_t)32 * HID * 12)             // 393216
#define NPREP ((NXV + NWV + NOV + NPW + 255) / 256)

__global__ void __launch_bounds__(256) k_prep(const float* __restrict__ X,
                                              const float* __restrict__ Win,
                                              const float* __restrict__ Wo,
                                              const float* __restrict__ Wh) {
    if (blockIdx.x == 0 && threadIdx.x < 128) g_bars[threadIdx.x] = 0u;
    size_t vi = (size_t)blockIdx.x * 256 + threadIdx.x;
    uint4 H, L;
    if (vi < NXV) {
        size_t i = vi * 8;
        split8(X + i, H, L);
        *reinterpret_cast<uint4*>(g_x_hi + i) = H;
        *reinterpret_cast<uint4*>(g_x_lo + i) = L;
    } else if (vi < NXV + NWV) {
        size_t i = (vi - NXV) * 8;
        split8(Win + i, H, L);
        *reinterpret_cast<uint4*>(g_win_hi + i) = H;
        *reinterpret_cast<uint4*>(g_win_lo + i) = L;
    } else if (vi < NXV + NWV + NOV) {
        size_t i = (vi - NXV - NWV) * 8;
        split8(Wo + i, H, L);
        *reinterpret_cast<uint4*>(g_wo_hi + i) = H;
        *reinterpret_cast<uint4*>(g_wo_lo + i) = L;
    } else if (vi < NXV + NWV + NOV + NPW) {
        size_t v2 = vi - NXV - NWV - NOV;
        int s = (int)(v2 / (HID * 12));
        int rem = (int)(v2 % (HID * 12));
        int k = rem / 12;
        int c8 = (rem % 12) * 8;
        int sub = c8 / 48, r2 = c8 % 48;
        int gate = r2 / 16, h0i = r2 % 16;
        const float* src = Wh + (size_t)k * G3 + gate * HID + s * 32 + sub * 16 + h0i;
        split8(src, H, L);
        size_t d = ((size_t)s * HID + k) * 96 + c8;
        *reinterpret_cast<uint4*>(g_wBp_hi + d) = H;
        *reinterpret_cast<uint4*>(g_wBp_lo + d) = L;
    }
}

// ===========================================================================
// k_h0_mma2 (unchanged from R16)
// ===========================================================================
#define H_AH 0
#define H_AL 4608
#define H_BH 9216
#define H_BL 18432
#define HSTG2 27648
#define SMEM_H0 (3 * HSTG2)

__global__ void __launch_bounds__(256) k_h0_mma2(float* __restrict__ H0P) {
    extern __shared__ char smem[];
    const uint32_t sb = smem_u32(smem);
    const int tid = threadIdx.x;
    const int w = tid >> 5, l = tid & 31;
    const int wm = w & 1;
    const int wn = w >> 1;
    const int lr = l >> 2;
    const int lc2 = (l & 3) * 2;
    const int m0 = blockIdx.y * 32, n0 = blockIdx.x * 64;
    const int z = blockIdx.z;
    const int c0 = z ? 63 : 0;
    const int nch = z ? 62 : 63;

    const int a_row  = wm * 16 + (l & 15);
    const int a_koff = (l >> 4) * 8;
    const int b_krow = l & 15;
    const int b_lhalf = (l >> 4) * 8;

    const char* srcAH = (const char*)(g_x_hi + (size_t)m0 * KIN);
    const char* srcAL = (const char*)(g_x_lo + (size_t)m0 * KIN);

    auto load = [&](int cha, int st) {
        uint32_t base = sb + st * HSTG2;
        {
            int r = tid >> 3, sg = tid & 7;
            CP16(base + H_AH + r * 144 + sg * 16,
                 srcAH + (size_t)r * (KIN * 2) + cha * 128 + sg * 16);
            CP16(base + H_AL + r * 144 + sg * 16,
                 srcAL + (size_t)r * (KIN * 2) + cha * 128 + sg * 16);
        }
        #pragma unroll
        for (int i = tid; i < 512; i += 256) {
            int r = i >> 3, sg = i & 7;
            CP16(base + H_BH + r * 144 + sg * 16,
                 (const char*)g_win_hi + ((size_t)(cha * 64 + r) * HID + n0) * 2 + sg * 16);
            CP16(base + H_BL + r * 144 + sg * 16,
                 (const char*)g_win_lo + ((size_t)(cha * 64 + r) * HID + n0) * 2 + sg * 16);
        }
    };

    load(c0 + 0, 0); CP_COMMIT();
    load(c0 + 1, 1); CP_COMMIT();

    float c[2][4] = {};

    auto compute = [&](int st) {
        uint32_t base = sb + st * HSTG2;
        #pragma unroll
        for (int kk = 0; kk < 4; kk++) {
            const int k0 = kk * 16;
            uint32_t aH[4], aL[4];
            uint32_t adA = base + H_AH + a_row * 144 + (k0 + a_koff) * 2;
            LDSM4(aH, adA);
            LDSM4(aL, adA + (H_AL - H_AH));
            uint32_t bH[2][2], bL[2][2];
            uint32_t adB = base + H_BH + (k0 + b_krow) * 144 + (wn * 16 + b_lhalf) * 2;
            uint32_t r4[4];
            LDSM4T(r4, adB);
            bH[0][0] = r4[0]; bH[0][1] = r4[1]; bH[1][0] = r4[2]; bH[1][1] = r4[3];
            LDSM4T(r4, adB + (H_BL - H_BH));
            bL[0][0] = r4[0]; bL[0][1] = r4[1]; bL[1][0] = r4[2]; bL[1][1] = r4[3];
            #pragma unroll
            for (int g = 0; g < 2; g++) {
                mma16816(c[g], aH, bH[g]);
                mma16816(c[g], aH, bL[g]);
                mma16816(c[g], aL, bH[g]);
            }
        }
    };

    #pragma unroll 1
    for (int ch = 0; ch < nch; ch++) {
        CP_WAIT(1);
        __syncthreads();
        compute(ch % 3);
        if (ch + 2 < nch) load(c0 + ch + 2, (ch + 2) % 3);
        CP_COMMIT();
    }

    float* dst = H0P + (size_t)z * BS * HID;
    #pragma unroll
    for (int g = 0; g < 2; g++) {
        const int col = n0 + wn * 16 + g * 8 + lc2;
        #pragma unroll
        for (int rr = 0; rr < 2; rr++) {
            const int m = m0 + wm * 16 + lr + rr * 8;
            *reinterpret_cast<float2*>(dst + (size_t)m * HID + col) =
                make_float2(c[g][2 * rr], c[g][2 * rr + 1]);
        }
    }
}

// ===========================================================================
// k_h0fix (unchanged)
// ===========================================================================
__global__ void __launch_bounds__(256) k_h0fix(const float* __restrict__ b_in) {
    size_t i = ((size_t)blockIdx.x * 256 + threadIdx.x) * 8;
    float r[8];
    #pragma unroll
    for (int j = 0; j < 8; j += 4) {
        float4 a = *reinterpret_cast<const float4*>(g_h0p + i + j);
        float4 b = *reinterpret_cast<const float4*>(g_h0p + BS * HID + i + j);
        float4 bb = *reinterpret_cast<const float4*>(b_in + ((i + j) & (HID - 1)));
        r[j + 0] = a.x + b.x + bb.x;
        r[j + 1] = a.y + b.y + bb.y;
        r[j + 2] = a.z + b.z + bb.z;
        r[j + 3] = a.w + b.w + bb.w;
    }
    #pragma unroll
    for (int j = 0; j < 8; j++) r[j] = r[j] > 0.f ? r[j] : 0.f;
    *reinterpret_cast<float4*>(g_h0 + i)     = make_float4(r[0], r[1], r[2], r[3]);
    *reinterpret_cast<float4*>(g_h0 + i + 4) = make_float4(r[4], r[5], r[6], r[7]);
    uint4 H, L;
    unsigned short* ph = (unsigned short*)&H;
    unsigned short* pl = (unsigned short*)&L;
    #pragma unroll
    for (int j = 0; j < 8; j++) split2(r[j], ph[j], pl[j]);
    *reinterpret_cast<uint4*>(g_h0b_hi + i) = H;
    *reinterpret_cast<uint4*>(g_h0b_lo + i) = L;
}

// ===========================================================================
// k_steps_mma v10: BK=128, 2-stage pipeline (8 chunks, 8 syncs/step).
// Warp grid 2m x 2n x 2k. Reduction buffer lives in stage-0 A region.
// ===========================================================================
#define OFF_AH 0
#define OFF_AL 17408
#define OFF_BH 34816
#define OFF_BL 61440
#define STG_B  88064
#define APITCH_B 272            // 17 x 16B (odd)
#define BPITCH_B 208            // 13 x 16B (odd)
#define SM_WI  (2 * STG_B)                  // 176128
#define SM_AS  (SM_WI + 96 * 36 * 4)        // 189952
#define SMEM_MMA (SM_AS + 2 * 64 * 36 * 4)  // 208384 B

__global__ void __launch_bounds__(256, 1) k_steps_mma(const float* __restrict__ h0,
                                                      const float* __restrict__ action,
                                                      const float* __restrict__ Wi,
                                                      const float* __restrict__ bi,
                                                      const float* __restrict__ bhn) {
    extern __shared__ char smem[];
    const uint32_t sb = smem_u32(smem);
    float* wi_s = reinterpret_cast<float*>(smem + SM_WI);
    float* a_s  = reinterpret_cast<float*>(smem + SM_AS);
    float* red  = reinterpret_cast<float*>(smem + OFF_AH);   // stage-0 A region

    const int tid = threadIdx.x;
    const int w = tid >> 5, l = tid & 31;
    const int s = blockIdx.x;
    const int mq = blockIdx.y;
    const int wm = w & 1;
    const int wn = (w >> 1) & 1;
    const int wk = w >> 2;
    const int lr = l >> 2;
    const int lc2 = (l & 3) * 2;

    const int a_koff = (l >> 4) * 8;
    const int b_krow = l & 15;
    const int b_noff = wn * 48 + (l >> 4) * 8;

    const int hidbase = s * 32 + wn * 16;

    float bh[2][2];
    #pragma unroll
    for (int pp = 0; pp < 2; pp++) {
        float2 v = *reinterpret_cast<const float2*>(bhn + hidbase + pp * 8 + lc2);
        bh[pp][0] = v.x; bh[pp][1] = v.y;
    }
    float hpreg[2][2][2][2];
    #pragma unroll
    for (int mb = 0; mb < 2; mb++)
        #pragma unroll
        for (int rr = 0; rr < 2; rr++) {
            const int m = mq * 64 + wm * 32 + mb * 16 + rr * 8 + lr;
            #pragma unroll
            for (int pp = 0; pp < 2; pp++) {
                float2 v = *reinterpret_cast<const float2*>(h0 + (size_t)m * HID + hidbase + pp * 8 + lc2);
                hpreg[mb][rr][pp][0] = v.x; hpreg[mb][rr][pp][1] = v.y;
            }
        }

    for (int i = tid; i < 96 * 32; i += 256) {
        int col = i >> 5, k = i & 31;
        int gate = col >> 5, cl = col & 31;
        wi_s[col * 36 + k] = Wi[(size_t)k * G3 + gate * HID + s * 32 + cl];
    }
    __syncthreads();

    const char* srcBH = (const char*)(g_wBp_hi + (size_t)s * HID * 96);
    const char* srcBL = (const char*)(g_wBp_lo + (size_t)s * HID * 96);

    auto load_B = [&](int ch, int st) {   // 128 k-rows x 192B, hi+lo
        uint32_t base = sb + st * STG_B;
        #pragma unroll
        for (int i = tid; i < 1536; i += 256) {
            int r = i / 12, sg = i % 12;
            CP16(base + OFF_BH + r * BPITCH_B + sg * 16,
                 srcBH + ((size_t)(ch * 128 + r)) * 192 + sg * 16);
            CP16(base + OFF_BL + r * BPITCH_B + sg * 16,
                 srcBL + ((size_t)(ch * 128 + r)) * 192 + sg * 16);
        }
    };
    auto load_act = [&](int tt) {
        uint32_t ab2 = sb + SM_AS + (tt & 1) * (64 * 36 * 4);
        #pragma unroll
        for (int i = tid; i < 512; i += 256) {
            int row = i >> 3, seg = i & 7;
            const float* src = action + ((size_t)(mq * 64 + row) * NT + tt) * ACT + seg * 4;
            CP16(ab2 + row * 144 + seg * 16, src);
        }
    };

    // step-0 prefetch: B(0)+act, B(1)
    load_B(0, 0); load_act(0); CP_COMMIT();
    load_B(1, 1); CP_COMMIT();

    #pragma unroll 1
    for (int t = 0; t < NT; t++) {
        const unsigned short* hsH = (t == 0) ? g_h0b_hi : g_obf_hi + (size_t)(t - 1) * BS * HID;
        const unsigned short* hsL = (t == 0) ? g_h0b_lo : g_obf_lo + (size_t)(t - 1) * BS * HID;
        const char* srcAH = (const char*)(hsH + (size_t)mq * 64 * HID);
        const char* srcAL = (const char*)(hsL + (size_t)mq * 64 * HID);

        auto load_A = [&](int ch, int st) {   // 64 rows x 256B, hi+lo
            uint32_t base = sb + st * STG_B;
            #pragma unroll
            for (int i = tid; i < 1024; i += 256) {
                int row = i >> 4, seg = i & 15;
                CP16(base + OFF_AH + row * APITCH_B + seg * 16,
                     srcAH + (size_t)row * (HID * 2) + ch * 256 + seg * 16);
                CP16(base + OFF_AL + row * APITCH_B + seg * 16,
                     srcAL + (size_t)row * (HID * 2) + ch * 256 + seg * 16);
            }
        };

        if (t > 0) {
            if (tid == 0) {
                unsigned* ctr = &g_bars[mq * 32];
                const unsigned target = 32u * (unsigned)t;
                atomicAdd(ctr, 1u);
                unsigned v;
                do {
                    asm volatile("ld.volatile.global.u32 %0, [%1];" : "=r"(v) : "l"(ctr));
                } while (v < target);
            }
            __syncthreads();
            __threadfence();
        }

        load_A(0, 0); CP_COMMIT();

        float giv[4][12];
        #pragma unroll
        for (int gate = 0; gate < 3; gate++)
            #pragma unroll
            for (int pp = 0; pp < 2; pp++) {
                float2 v = *reinterpret_cast<const float2*>(bi + gate * HID + hidbase + pp * 8 + lc2);
                #pragma unroll
                for (int mr = 0; mr < 4; mr++) {
                    giv[mr][gate * 4 + pp * 2 + 0] = v.x;
                    giv[mr][gate * 4 + pp * 2 + 1] = v.y;
                }
            }

        const float* ab = a_s + (t & 1) * (64 * 36);

        auto gi_piece = [&](int k4) {
            float4 a[4];
            #pragma unroll
            for (int mr = 0; mr < 4; mr++)
                a[mr] = *reinterpret_cast<const float4*>(
                    ab + (wm * 32 + (mr >> 1) * 16 + (mr & 1) * 8 + lr) * 36 + k4 * 4);
            #pragma unroll
            for (int gate = 0; gate < 3; gate++)
                #pragma unroll
                for (int pp = 0; pp < 2; pp++)
                    #pragma unroll
                    for (int e = 0; e < 2; e++) {
                        int col = gate * 32 + wn * 16 + pp * 8 + lc2 + e;
                        float4 wv = *reinterpret_cast<const float4*>(wi_s + col * 36 + k4 * 4);
                        int j = gate * 4 + pp * 2 + e;
                        #pragma unroll
                        for (int mr = 0; mr < 4; mr++)
                            giv[mr][j] += a[mr].x * wv.x + a[mr].y * wv.y
                                        + a[mr].z * wv.z + a[mr].w * wv.w;
                    }
        };

        float c[6][2][4] = {};

        auto compute = [&](int st) {
            uint32_t base = sb + st * STG_B;
            #pragma unroll
            for (int kki = 0; kki < 4; kki++) {
                const int k0 = (wk * 4 + kki) * 16;
                uint32_t aH[2][4], aL[2][4];
                #pragma unroll
                for (int mb = 0; mb < 2; mb++) {
                    uint32_t adA = base + OFF_AH
                                 + (wm * 32 + mb * 16 + (l & 15)) * APITCH_B
                                 + (k0 + a_koff) * 2;
                    LDSM4(aH[mb], adA);
                    LDSM4(aL[mb], adA + (OFF_AL - OFF_AH));
                }
                uint32_t bH[6][2], bL[6][2];
                #pragma unroll
                for (int g2 = 0; g2 < 3; g2++) {
                    uint32_t adB = base + OFF_BH + (k0 + b_krow) * BPITCH_B + (b_noff + g2 * 16) * 2;
                    uint32_t r4[4];
                    LDSM4T(r4, adB);
                    bH[g2 * 2][0] = r4[0]; bH[g2 * 2][1] = r4[1];
                    bH[g2 * 2 + 1][0] = r4[2]; bH[g2 * 2 + 1][1] = r4[3];
                    LDSM4T(r4, adB + (OFF_BL - OFF_BH));
                    bL[g2 * 2][0] = r4[0]; bL[g2 * 2][1] = r4[1];
                    bL[g2 * 2 + 1][0] = r4[2]; bL[g2 * 2 + 1][1] = r4[3];
                }
                #pragma unroll
                for (int g = 0; g < 6; g++)
                    #pragma unroll
                    for (int mb = 0; mb < 2; mb++) {
                        mma16816(c[g][mb], aH[mb], bH[g]);
                        mma16816(c[g][mb], aH[mb], bL[g]);
                        mma16816(c[g][mb], aL[mb], bH[g]);
                    }
            }
        };

        #pragma unroll 1
        for (int ch = 0; ch < 8; ch++) {
            CP_WAIT(0);
            __syncthreads();
            if (ch + 1 < 8) {
                int st2 = (ch + 1) & 1;
                load_A(ch + 1, st2);
                if (ch >= 1) load_B(ch + 1, st2);   // B(1) preloaded
            }
            CP_COMMIT();
            compute(ch & 1);
            if (wk == 0) gi_piece(ch);
        }
        CP_WAIT(0);
        __syncthreads();   // all computes done; both stages free

        // wk==1 warps dump partials into stage-0 A region (reused as red)
        if (wk == 1) {
            int slot = ((w & 3) * 32 + l) * 52;
            #pragma unroll
            for (int g = 0; g < 6; g++)
                #pragma unroll
                for (int mb = 0; mb < 2; mb++)
                    *reinterpret_cast<float4*>(red + slot + (g * 2 + mb) * 4) =
                        *reinterpret_cast<const float4*>(c[g][mb]);
        }

        if (t + 1 < NT) {
            load_B(0, 0); load_act(t + 1); CP_COMMIT();
            load_B(1, 1); CP_COMMIT();
        }
        __syncthreads();   // partials visible

        if (wk == 0) {
            int slot = ((w & 3) * 32 + l) * 52;
            #pragma unroll
            for (int g = 0; g < 6; g++)
                #pragma unroll
                for (int mb = 0; mb < 2; mb++) {
                    float4 p = *reinterpret_cast<const float4*>(red + slot + (g * 2 + mb) * 4);
                    c[g][mb][0] += p.x; c[g][mb][1] += p.y;
                    c[g][mb][2] += p.z; c[g][mb][3] += p.w;
                }

            #pragma unroll
            for (int mb = 0; mb < 2; mb++)
                #pragma unroll
                for (int rr = 0; rr < 2; rr++) {
                    const int m = mq * 64 + wm * 32 + mb * 16 + rr * 8 + lr;
                    const int mr = mb * 2 + rr;
                    #pragma unroll
                    for (int pp = 0; pp < 2; pp++) {
                        const int hid = hidbase + pp * 8 + lc2;
                        float h[2];
                        #pragma unroll
                        for (int e = 0; e < 2; e++) {
                            float rv = c[0 + pp][mb][2 * rr + e];
                            float zv = c[2 + pp][mb][2 * rr + e];
                            float nv = c[4 + pp][mb][2 * rr + e];
                            float rg = fast_sigmoid(rv + giv[mr][0 * 4 + pp * 2 + e]);
                            float zg = fast_sigmoid(zv + giv[mr][1 * 4 + pp * 2 + e]);
                            float ng = fast_tanh(giv[mr][2 * 4 + pp * 2 + e] + rg * (nv + bh[pp][e]));
                            h[e] = (1.0f - zg) * ng + zg * hpreg[mb][rr][pp][e];
                            hpreg[mb][rr][pp][e] = h[e];
                        }
                        size_t d = ((size_t)t * BS + m) * HID + hid;
                        unsigned short hi0, hi1, lo0, lo1;
                        split2(h[0], hi0, lo0);
                        split2(h[1], hi1, lo1);
                        *reinterpret_cast<uint32_t*>(g_obf_hi + d) = ((uint32_t)hi1 << 16) | hi0;
                        *reinterpret_cast<uint32_t*>(g_obf_lo + d) = ((uint32_t)lo1 << 16) | lo0;
                    }
                }
        }

        if (t + 1 < NT) {
            __threadfence();
            __syncthreads();
        }
    }
}

// ===========================================================================
// k_out_mma (unchanged from R16)
// ===========================================================================
#define O_AH 0
#define O_AL 9216
#define O_BH 18432
#define O_BL 27648
#define OSTG 36864
#define O_PITCH 144
#define SMEM_OUT (3 * OSTG)

__global__ void __launch_bounds__(256) k_out_mma(const float* __restrict__ bo,
                                                 float* __restrict__ out) {
    extern __shared__ char smem[];
    const uint32_t sb = smem_u32(smem);
    const int tid = threadIdx.x;
    const int w = tid >> 5, l = tid & 31;
    const int wm = w & 3;
    const int wn = w >> 2;
    const int lr = l >> 2;
    const int lc2 = (l & 3) * 2;
    const int R0 = blockIdx.x * 64;

    const int a_row  = wm * 16 + (l & 15);
    const int a_koff = (l >> 4) * 8;
    const int b_krow = l & 15;
    const int b_lhalf = (l >> 4) * 8;

    const char* srcAH = (const char*)(g_obf_hi + (size_t)R0 * HID);
    const char* srcAL = (const char*)(g_obf_lo + (size_t)R0 * HID);

    auto load = [&](int ch, int st) {
        uint32_t base = sb + st * OSTG;
        #pragma unroll
        for (int i = tid; i < 512; i += 256) {
            int r = i >> 3, sg = i & 7;
            CP16(base + O_AH + r * O_PITCH + sg * 16,
                 srcAH + (size_t)r * (HID * 2) + ch * 128 + sg * 16);
            CP16(base + O_AL + r * O_PITCH + sg * 16,
                 srcAL + (size_t)r * (HID * 2) + ch * 128 + sg * 16);
        }
        #pragma unroll
        for (int i = tid; i < 512; i += 256) {
            int r = i >> 3, sg = i & 7;
            CP16(base + O_BH + r * O_PITCH + sg * 16,
                 (const char*)g_wo_hi + ((size_t)(ch * 64 + r) * OUTD) * 2 + sg * 16);
            CP16(base + O_BL + r * O_PITCH + sg * 16,
                 (const char*)g_wo_lo + ((size_t)(ch * 64 + r) * OUTD) * 2 + sg * 16);
        }
    };

    load(0, 0); CP_COMMIT();
    load(1, 1); CP_COMMIT();

    float c[4][4] = {};

    auto compute = [&](int st) {
        uint32_t base = sb + st * OSTG;
        #pragma unroll
        for (int kk = 0; kk < 4; kk++) {
            const int k0 = kk * 16;
            uint32_t aH[4], aL[4];
            uint32_t adA = base + O_AH + a_row * O_PITCH + (k0 + a_koff) * 2;
            LDSM4(aH, adA);
            LDSM4(aL, adA + (O_AL - O_AH));
            uint32_t bH[4][2], bL[4][2];
            #pragma unroll
            for (int n16 = 0; n16 < 2; n16++) {
                uint32_t adB = base + O_BH + (k0 + b_krow) * O_PITCH
                             + (wn * 32 + n16 * 16 + b_lhalf) * 2;
                uint32_t r4[4];
                LDSM4T(r4, adB);
                bH[n16 * 2][0] = r4[0]; bH[n16 * 2][1] = r4[1];
                bH[n16 * 2 + 1][0] = r4[2]; bH[n16 * 2 + 1][1] = r4[3];
                LDSM4T(r4, adB + (O_BL - O_BH));
                bL[n16 * 2][0] = r4[0]; bL[n16 * 2][1] = r4[1];
                bL[n16 * 2 + 1][0] = r4[2]; bL[n16 * 2 + 1][1] = r4[3];
            }
            #pragma unroll
            for (int g = 0; g < 4; g++) {
                mma16816(c[g], aH, bH[g]);
                mma16816(c[g], aH, bL[g]);
                mma16816(c[g], aL, bH[g]);
            }
        }
    };

    #pragma unroll 1
    for (int ch = 0; ch < 16; ch++) {
        CP_WAIT(1);
        __syncthreads();
        compute(ch % 3);
        if (ch + 2 < 16) load(ch + 2, (ch + 2) % 3);
        CP_COMMIT();
    }

    #pragma unroll
    for (int g = 0; g < 4; g++) {
        const int col = wn * 32 + g * 8 + lc2;
        float2 bov = *reinterpret_cast<const float2*>(bo + col);
        #pragma unroll
        for (int rr = 0; rr < 2; rr++) {
            int R = R0 + wm * 16 + lr + rr * 8;
            int tt = R >> 8;
            int b  = R & (BS - 1);
            float2 o = make_float2(c[g][2 * rr] + bov.x, c[g][2 * rr + 1] + bov.y);
            *reinterpret_cast<float2*>(out + ((size_t)b * NT + tt) * OUTD + col) = o;
        }
    }
}

extern "C" void kernel_launch(void* const* d_in, const int* in_sizes, int n_in,
                              void* d_out, int out_size) {
    const float* history = (const float*)d_in[0];
    const float* action  = (const float*)d_in[1];
    const float* W_in    = (const float*)d_in[2];
    const float* b_in    = (const float*)d_in[3];
    const float* Wi      = (const float*)d_in[4];
    const float* bi      = (const float*)d_in[5];
    const float* Wh      = (const float*)d_in[6];
    const float* bhn     = (const float*)d_in[7];
    const float* Wo      = (const float*)d_in[8];
    const float* bo      = (const float*)d_in[9];
    float* out = (float*)d_out;

    float *h0buf = nullptr, *h0pbuf = nullptr;
    cudaGetSymbolAddress((void**)&h0buf, g_h0);
    cudaGetSymbolAddress((void**)&h0pbuf, g_h0p);

    cudaFuncSetAttribute(k_h0_mma2, cudaFuncAttributeMaxDynamicSharedMemorySize, SMEM_H0);
    cudaFuncSetAttribute(k_steps_mma, cudaFuncAttributeMaxDynamicSharedMemorySize, SMEM_MMA);
    cudaFuncSetAttribute(k_out_mma, cudaFuncAttributeMaxDynamicSharedMemorySize, SMEM_OUT);

    k_prep<<<(int)NPREP, 256>>>(history, W_in, Wo, Wh);

    k_h0_mma2<<<dim3(HID / 64, BS / 32, 2), 256, SMEM_H0>>>(h0pbuf);
    k_h0fix<<<BS * HID / (256 * 8), 256>>>(b_in);

    k_steps_mma<<<dim3(32, 4), 256, SMEM_MMA>>>(h0buf, action, Wi, bi, bhn);

    k_out_mma<<<NT * BS / 64, 256, SMEM_OUT>>>(bo, out);
}